// round 10
// baseline (speedup 1.0000x reference)
#include <cuda_runtime.h>
#include <cstdint>

// ---------------- problem constants ----------------
#define NELEM 64
#define BMAX  16384
#define INSZ  448
#define WSZ   14336
// seg0: mi=96, mo=96, d=1, w_off=0,     x_off=0
// seg1: mi=64, mo=64, d=3, w_off=9216,  x_off=96
// seg2: mi=32, mo=32, d=5, w_off=13312, x_off=288
// SMEM transposed W layout per element: [o][i], i-stride padded to ≡4 (mod 32)
// so LDS.128 (16B) per lane is conflict-free AND 16B-aligned:
//   seg0: 96 rows stride 100 -> [0, 9600)
//   seg1: 64 rows stride  68 -> [9600, 13952)
//   seg2: 32 rows stride  36 -> [13952, 15104)
#define WT_S1 9600
#define WT_S2 13952
#define WTOT  15104

#define R_ROWS 6
#define WARPS  4
// 296 CTAs = 2 per SM on 148 SMs (single wave; also single wave on 152-SM GB300).
// e = blockIdx.x & 63, chunk = blockIdx.x >> 6. Elements 0..39 get 5 chunks,
// elements 40..63 get 4 chunks (296 = 64*4 + 40).
#define GRIDX 296
#define SMEM_FLOATS (WTOT + WARPS * R_ROWS * INSZ)
#define SMEM_BYTES  (SMEM_FLOATS * 4)

// ---------------- scratch (no allocation allowed) ----------------
__device__ int g_counts[NELEM];
__device__ int g_rows[NELEM * BMAX];   // fixed per-element bucket regions (4 MB)

// ---------------- helpers ----------------
__device__ __forceinline__ ulonglong2 ld128(const float* p) {
    return *reinterpret_cast<const ulonglong2*>(p);
}
__device__ __forceinline__ unsigned long long ffma2(unsigned long long x,
                                                    unsigned long long w,
                                                    unsigned long long a) {
    unsigned long long d;
    asm("fma.rn.f32x2 %0, %1, %2, %3;" : "=l"(d) : "l"(x), "l"(w), "l"(a));
    return d;
}
__device__ __forceinline__ float hsum2(unsigned long long a) {
    float lo, hi;
    asm("mov.b64 {%0,%1}, %2;" : "=f"(lo), "=f"(hi) : "l"(a));
    return lo + hi;
}
// streaming (evict-first) global accesses: x read-once, y write-only
__device__ __forceinline__ float4 ldcs128(const float4* p) { return __ldcs(p); }
__device__ __forceinline__ float  ldcs32(const float* p)  { return __ldcs(p); }
__device__ __forceinline__ void   stcs32(float* p, float v) { __stcs(p, v); }

// ---------------- prep: parallel bucket build, dtype-agnostic ----------------
// The reference requests int64 indices but JAX without x64 silently emits
// int32 — so detect the element width at runtime. Read the buffer as int32:
// little-endian int64 values in [0,64) have ALL high words == 0; genuine
// int32 index data has nonzero odd positions with overwhelming probability
// (P[all 512 zero] = 64^-512). Branch per block on the detected width.
// Block e scans all indices and compacts matching row ids into its own fixed
// region g_rows[e*BMAX ..] via ballot/popc (1 smem atomic per warp-iter).
__global__ void k_bucket(const int* __restrict__ idx32, int B) {
    __shared__ int cnt;
    __shared__ int s_is64;
    const int e = blockIdx.x;
    const int tid = threadIdx.x;
    if (tid == 0) { cnt = 0; s_is64 = 1; }
    __syncthreads();
    // dtype probe: odd int32 positions of the first 512 candidate int64s.
    // Safe in both cases: max probed int32 index 1025 < B.
    int bad = 0;
    for (int t = tid; t < 512; t += blockDim.x)
        if (idx32[2 * t + 1] != 0) bad = 1;
    if (bad) atomicExch(&s_is64, 0);
    __syncthreads();
    const int is64 = s_is64;

    const int lane = tid & 31;
    for (int jb = tid - lane; jb < B; jb += blockDim.x) {
        int j = jb + lane;
        int v = -1;
        if (j < B) v = is64 ? idx32[2 * j] : idx32[j];
        bool m = (v == e);
        unsigned mask = __ballot_sync(0xffffffffu, m);
        int nw = __popc(mask);
        int base = 0;
        if (lane == 0 && nw) base = atomicAdd(&cnt, nw);
        base = __shfl_sync(0xffffffffu, base, 0);
        if (m)
            g_rows[e * BMAX + base + __popc(mask & ((1u << lane) - 1u))] = j;
    }
    __syncthreads();
    if (tid == 0) g_counts[e] = cnt;
}

// ---------------- compute kernel ----------------
// 296 CTAs, 128 threads, 2 CTAs/SM. Each CTA transposes W_e from global into a
// conflict-free SMEM layout; each warp processes R_ROWS rows at a time with
// packed fma.rn.f32x2. All SMEM reads are 16B (LDS.128): W via stride≡4(mod 32)
// padding, x via broadcast v4 loads of 2 i-pairs. x/y use streaming cache
// hints so W + g_rows keep L2 residency.
__global__ __launch_bounds__(128, 2)
void k_compute(const float* __restrict__ W, const float* __restrict__ x,
               float* __restrict__ y) {
    extern __shared__ float sm[];
    float* sW = sm;
    const int e      = blockIdx.x & 63;
    const int chunk  = blockIdx.x >> 6;
    const int nchunk = (e < (GRIDX - NELEM * 4)) ? 5 : 4;
    const int tid  = threadIdx.x;
    const int lane = tid & 31;
    const int warp = tid >> 5;

    // ---- load + transpose W_e: raw [i*mo+o] -> SMEM [o][i] padded ----
    {
        const float4* wsrc = reinterpret_cast<const float4*>(W + (size_t)e * WSZ);
        for (int t4 = tid; t4 < WSZ / 4; t4 += 128) {
            float4 v = wsrc[t4];
            int q = t4 << 2;
            int base, str;
            if (q < 9216) {                 // seg0: mi=96, mo=96
                int i = q / 96, o = q - i * 96;
                base = o * 100 + i; str = 100;
            } else if (q < 13312) {         // seg1: mi=64, mo=64
                int q2 = q - 9216;
                int i = q2 >> 6, o = q2 & 63;
                base = WT_S1 + o * 68 + i; str = 68;
            } else {                        // seg2: mi=32, mo=32
                int q2 = q - 13312;
                int i = q2 >> 5, o = q2 & 31;
                base = WT_S2 + o * 36 + i; str = 36;
            }
            sW[base]           = v.x;
            sW[base + str]     = v.y;
            sW[base + 2 * str] = v.z;
            sW[base + 3 * str] = v.w;
        }
    }
    __syncthreads();

    const int off = e * BMAX;
    const int cnt = g_counts[e];
    float* xw = sm + WTOT + warp * (R_ROWS * INSZ);

    for (int g = chunk * WARPS + warp; g * R_ROWS < cnt; g += nchunk * WARPS) {
        int  rows[R_ROWS];
        bool val[R_ROWS];
#pragma unroll
        for (int r = 0; r < R_ROWS; r++) {
            int li = g * R_ROWS + r;
            val[r]  = li < cnt;
            rows[r] = g_rows[off + (val[r] ? li : (cnt - 1))];
        }

        // ---- stage x rows into SMEM (seg1/seg2 transposed to m-major) ----
#pragma unroll
        for (int r = 0; r < R_ROWS; r++) {
            const float* xg = x + (size_t)rows[r] * INSZ;
            float* xs = xw + r * INSZ;
            if (lane < 24)
                reinterpret_cast<float4*>(xs)[lane] =
                    ldcs128(reinterpret_cast<const float4*>(xg) + lane); // seg0
#pragma unroll
            for (int u = 0; u < 6; u++) {                        // seg1: 192
                int t = lane + u * 32;
                int i = t / 3, m = t - 3 * i;
                xs[96 + m * 64 + i] = ldcs32(xg + 96 + t);
            }
#pragma unroll
            for (int u = 0; u < 5; u++) {                        // seg2: 160
                int t = lane + u * 32;
                int i = t / 5, m = t - 5 * i;
                xs[288 + m * 32 + i] = ldcs32(xg + 288 + t);
            }
        }
        __syncwarp();

        // ================= seg0: mi=96, mo=96, d=1 =================
        {
            unsigned long long acc[3][R_ROWS];
#pragma unroll
            for (int s = 0; s < 3; s++)
#pragma unroll
                for (int r = 0; r < R_ROWS; r++) acc[s][r] = 0ull;
            const float* w0 = sW + lane * 100;
            const float* w1 = sW + (lane + 32) * 100;
            const float* w2 = sW + (lane + 64) * 100;
#pragma unroll 4
            for (int i4 = 0; i4 < 24; i4++) {
                ulonglong2 a = ld128(w0 + 4 * i4);
                ulonglong2 b = ld128(w1 + 4 * i4);
                ulonglong2 c = ld128(w2 + 4 * i4);
#pragma unroll
                for (int r = 0; r < R_ROWS; r++) {
                    ulonglong2 xv = ld128(xw + r * INSZ + 4 * i4);
                    acc[0][r] = ffma2(xv.x, a.x, acc[0][r]);
                    acc[0][r] = ffma2(xv.y, a.y, acc[0][r]);
                    acc[1][r] = ffma2(xv.x, b.x, acc[1][r]);
                    acc[1][r] = ffma2(xv.y, b.y, acc[1][r]);
                    acc[2][r] = ffma2(xv.x, c.x, acc[2][r]);
                    acc[2][r] = ffma2(xv.y, c.y, acc[2][r]);
                }
            }
#pragma unroll
            for (int r = 0; r < R_ROWS; r++) {
                if (!val[r]) continue;
                float* yg = y + (size_t)rows[r] * INSZ;
                stcs32(yg + lane,      hsum2(acc[0][r]));
                stcs32(yg + lane + 32, hsum2(acc[1][r]));
                stcs32(yg + lane + 64, hsum2(acc[2][r]));
            }
        }

        // ================= seg1: mi=64, mo=64, d=3 =================
        {
            unsigned long long acc[2][3][R_ROWS];
#pragma unroll
            for (int s = 0; s < 2; s++)
#pragma unroll
                for (int m = 0; m < 3; m++)
#pragma unroll
                    for (int r = 0; r < R_ROWS; r++) acc[s][m][r] = 0ull;
            const float* wa = sW + WT_S1 + lane * 68;
            const float* wb = sW + WT_S1 + (lane + 32) * 68;
#pragma unroll 4
            for (int i4 = 0; i4 < 16; i4++) {
                ulonglong2 a = ld128(wa + 4 * i4);
                ulonglong2 b = ld128(wb + 4 * i4);
#pragma unroll
                for (int r = 0; r < R_ROWS; r++) {
#pragma unroll
                    for (int m = 0; m < 3; m++) {
                        ulonglong2 xv =
                            ld128(xw + r * INSZ + 96 + m * 64 + 4 * i4);
                        acc[0][m][r] = ffma2(xv.x, a.x, acc[0][m][r]);
                        acc[0][m][r] = ffma2(xv.y, a.y, acc[0][m][r]);
                        acc[1][m][r] = ffma2(xv.x, b.x, acc[1][m][r]);
                        acc[1][m][r] = ffma2(xv.y, b.y, acc[1][m][r]);
                    }
                }
            }
#pragma unroll
            for (int r = 0; r < R_ROWS; r++) {
                if (!val[r]) continue;
                float* yg = y + (size_t)rows[r] * INSZ;
#pragma unroll
                for (int m = 0; m < 3; m++) {
                    stcs32(yg + 96 + lane * 3 + m,        hsum2(acc[0][m][r]));
                    stcs32(yg + 96 + (lane + 32) * 3 + m, hsum2(acc[1][m][r]));
                }
            }
        }

        // ================= seg2: mi=32, mo=32, d=5 =================
        {
            unsigned long long acc[5][R_ROWS];
#pragma unroll
            for (int m = 0; m < 5; m++)
#pragma unroll
                for (int r = 0; r < R_ROWS; r++) acc[m][r] = 0ull;
            const float* wc = sW + WT_S2 + lane * 36;
#pragma unroll 4
            for (int i4 = 0; i4 < 8; i4++) {
                ulonglong2 a = ld128(wc + 4 * i4);
#pragma unroll
                for (int r = 0; r < R_ROWS; r++) {
#pragma unroll
                    for (int m = 0; m < 5; m++) {
                        ulonglong2 xv =
                            ld128(xw + r * INSZ + 288 + m * 32 + 4 * i4);
                        acc[m][r] = ffma2(xv.x, a.x, acc[m][r]);
                        acc[m][r] = ffma2(xv.y, a.y, acc[m][r]);
                    }
                }
            }
#pragma unroll
            for (int r = 0; r < R_ROWS; r++) {
                if (!val[r]) continue;
                float* yg = y + (size_t)rows[r] * INSZ;
#pragma unroll
                for (int m = 0; m < 5; m++)
                    stcs32(yg + 288 + lane * 5 + m, hsum2(acc[m][r]));
            }
        }
        __syncwarp();  // protect xw before next group's restage
    }
}

// ---------------- launch (2 kernels total) ----------------
extern "C" void kernel_launch(void* const* d_in, const int* in_sizes, int n_in,
                              void* d_out, int out_size) {
    const float* W     = (const float*)d_in[0];
    const float* x     = (const float*)d_in[1];
    const int*   idx32 = (const int*)d_in[2];   // int32 OR int64 (auto-detected)
    float*       y     = (float*)d_out;
    const int B = in_sizes[1] / INSZ;

    cudaFuncSetAttribute(k_compute, cudaFuncAttributeMaxDynamicSharedMemorySize,
                         SMEM_BYTES);

    k_bucket<<<NELEM, 512>>>(idx32, B);
    k_compute<<<GRIDX, 128, SMEM_BYTES>>>(W, x, y);
}